// round 1
// baseline (speedup 1.0000x reference)
#include <cuda_runtime.h>

// ConvCaps EM-routing: one warp per batch element.
// lane = hh*8 + c  (c = output capsule 0..7, hh = pose-row 0..3, lane owns h = hh*4 + j, j=0..3)
// B (input capsule, 8) lives in registers.
// Reductions: over C -> shfl.bfly xor {1,2,4}; over h -> xor {8,16}; over B -> register loop.

#define FULLMASK 0xffffffffu
#define EPSF     1e-8f
#define HALF_LN2PI 0.9189385332046727f  // 0.5*ln(2*pi)

static __global__ __launch_bounds__(256, 2)
void caps_kernel(const float* __restrict__ x,
                 const float* __restrict__ wts,
                 const float* __restrict__ bu_g,
                 const float* __restrict__ ba_g,
                 float* __restrict__ o1,   // p_out_p  [b][8][16]   (may be null)
                 float* __restrict__ o2,   // a_out_p  [b][8][1]    (may be null)
                 float* __restrict__ o3,   // out_p    [b][8][17]   (may be null)
                 float* __restrict__ o4,   // out      [b][136]     (may be null)
                 int batch)
{
    __shared__ float w_s[1024];     // [B][k][j][c] : transposed so lane-c reads are conflict-free
    __shared__ float bu_s[8];
    __shared__ float ba_s[8];
    __shared__ float xb[8][136];    // per-warp input stage

    const int tid  = threadIdx.x;
    const int warp = tid >> 5;
    const int lane = tid & 31;
    const int c    = lane & 7;
    const int hh   = lane >> 3;

    // stage weights transposed: w[B][c][k][j] -> w_s[((B*4+k)*4+j)*8 + c]
    #pragma unroll
    for (int t = 0; t < 4; ++t) {
        int e = tid + t * 256;
        int B = e >> 7, cc = (e >> 4) & 7, k = (e >> 2) & 3, j = e & 3;
        w_s[((B * 4 + k) * 4 + j) * 8 + cc] = wts[e];
    }
    if (tid < 8) { bu_s[tid] = bu_g[tid]; ba_s[tid] = ba_g[tid]; }

    const long long b = (long long)blockIdx.x * 8 + warp;
    const bool valid = (b < (long long)batch);
    if (valid) {
        const float* xg = x + b * 136;
        #pragma unroll
        for (int t = 0; t < 4; ++t) xb[warp][lane + 32 * t] = xg[lane + 32 * t];
        if (lane < 8) xb[warp][128 + lane] = xg[128 + lane];
    }
    __syncthreads();

    const float* xw = xb[warp];

    // activations a_in[B]
    float aB[8];
    #pragma unroll
    for (int B = 0; B < 8; ++B) aB[B] = xw[128 + B];

    // votes: v[B][c][h] for lane's c, h = hh*4+j.  v[b,B,c,i,j] = sum_k p[b,B,i,k]*W[B,c,k,j]
    float v[32];
    #pragma unroll
    for (int B = 0; B < 8; ++B) {
        const float p0 = xw[B * 16 + hh * 4 + 0];
        const float p1 = xw[B * 16 + hh * 4 + 1];
        const float p2 = xw[B * 16 + hh * 4 + 2];
        const float p3 = xw[B * 16 + hh * 4 + 3];
        const float* wb = &w_s[B * 128 + c];
        #pragma unroll
        for (int j = 0; j < 4; ++j) {
            float acc =      p0 * wb[(0 * 4 + j) * 8];
            acc = fmaf(p1, wb[(1 * 4 + j) * 8], acc);
            acc = fmaf(p2, wb[(2 * 4 + j) * 8], acc);
            acc = fmaf(p3, wb[(3 * 4 + j) * 8], acc);
            v[B * 4 + j] = acc;
        }
    }

    const float bu = bu_s[c];
    const float ba = ba_s[c];

    float r[8];
    #pragma unroll
    for (int B = 0; B < 8; ++B) r[B] = 0.125f;

    float mu[4];
    float a_out = 0.f;

    #pragma unroll
    for (int it = 0; it < 3; ++it) {
        // rr = r*a_in ; normalize over C ; coeff = rrn / (sum_B rrn + eps)
        float coeff[8];
        float r_sum = 0.f;
        #pragma unroll
        for (int B = 0; B < 8; ++B) {
            float rr = r[B] * aB[B];
            float d = rr;
            d += __shfl_xor_sync(FULLMASK, d, 1);
            d += __shfl_xor_sync(FULLMASK, d, 2);
            d += __shfl_xor_sync(FULLMASK, d, 4);
            float rrn = rr * __fdividef(1.f, d + EPSF);
            coeff[B] = rrn;
            r_sum += rrn;
        }
        const float invrs = __fdividef(1.f, r_sum + EPSF);
        #pragma unroll
        for (int B = 0; B < 8; ++B) coeff[B] *= invrs;

        // mu[c,h] = sum_B coeff*v
        #pragma unroll
        for (int j = 0; j < 4; ++j) mu[j] = 0.f;
        #pragma unroll
        for (int B = 0; B < 8; ++B) {
            #pragma unroll
            for (int j = 0; j < 4; ++j)
                mu[j] = fmaf(coeff[B], v[B * 4 + j], mu[j]);
        }

        // sigma^2[c,h] = sum_B coeff*(v-mu)^2 + eps
        float sig[4];
        #pragma unroll
        for (int j = 0; j < 4; ++j) sig[j] = EPSF;
        #pragma unroll
        for (int B = 0; B < 8; ++B) {
            #pragma unroll
            for (int j = 0; j < 4; ++j) {
                float d = v[B * 4 + j] - mu[j];
                sig[j] = fmaf(coeff[B] * d, d, sig[j]);
            }
        }

        // activation cost: sum_h (beta_u + 0.5*log sigma) * r_sum
        float hl[4], hpart = 0.f;
        #pragma unroll
        for (int j = 0; j < 4; ++j) {
            hl[j] = 0.5f * __logf(sig[j]);
            hpart += hl[j];
        }
        float Hs = hpart;
        Hs += __shfl_xor_sync(FULLMASK, Hs, 8);
        Hs += __shfl_xor_sync(FULLMASK, Hs, 16);

        const float cost = r_sum * (16.f * bu + Hs);
        const float z  = 1e-3f * (ba - cost);
        const float ez = __expf(-z);
        a_out = __fdividef(1.f, 1.f + ez);

        if (it < 2) {
            // ln_ap[B,c] = log(a_out[c]) - sum_h [ (v-mu)^2/(2 sig) + 0.5 log sig + 0.5 ln2pi ]
            const float la = -__logf(1.f + ez);          // log(sigmoid(z))
            const float Kc = la - Hs - 16.f * HALF_LN2PI;
            float is2[4];
            #pragma unroll
            for (int j = 0; j < 4; ++j) is2[j] = __fdividef(0.5f, sig[j]);

            float lnap[8];
            #pragma unroll
            for (int B = 0; B < 8; ++B) {
                float t = 0.f;
                #pragma unroll
                for (int j = 0; j < 4; ++j) {
                    float d = v[B * 4 + j] - mu[j];
                    t = fmaf(d * is2[j], d, t);
                }
                t += __shfl_xor_sync(FULLMASK, t, 8);
                t += __shfl_xor_sync(FULLMASK, t, 16);
                lnap[B] = Kc - t;
            }
            // r = softmax over C
            #pragma unroll
            for (int B = 0; B < 8; ++B) {
                float m = lnap[B];
                m = fmaxf(m, __shfl_xor_sync(FULLMASK, m, 1));
                m = fmaxf(m, __shfl_xor_sync(FULLMASK, m, 2));
                m = fmaxf(m, __shfl_xor_sync(FULLMASK, m, 4));
                float e = __expf(lnap[B] - m);
                float s = e;
                s += __shfl_xor_sync(FULLMASK, s, 1);
                s += __shfl_xor_sync(FULLMASK, s, 2);
                s += __shfl_xor_sync(FULLMASK, s, 4);
                r[B] = e * __fdividef(1.f, s);
            }
        }
    }

    if (!valid) return;

    const float4 m4 = make_float4(mu[0], mu[1], mu[2], mu[3]);

    if (o1) {   // p_out_p [b][c][16]
        *reinterpret_cast<float4*>(o1 + b * 128 + c * 16 + hh * 4) = m4;
    }
    if (o2 && hh == 0) {   // a_out_p [b][c]
        o2[b * 8 + c] = a_out;
    }
    if (o3) {   // out_p [b][c][17]
        float* p = o3 + b * 136 + c * 17 + hh * 4;
        p[0] = mu[0]; p[1] = mu[1]; p[2] = mu[2]; p[3] = mu[3];
        if (hh == 0) o3[b * 136 + c * 17 + 16] = a_out;
    }
    if (o4) {   // out [b][136] : 128 mu then 8 a_out
        *reinterpret_cast<float4*>(o4 + b * 136 + c * 16 + hh * 4) = m4;
        if (hh == 0) o4[b * 136 + 128 + c] = a_out;
    }
}

extern "C" void kernel_launch(void* const* d_in, const int* in_sizes, int n_in,
                              void* d_out, int out_size)
{
    const float* x  = (const float*)d_in[0];
    const float* w  = (const float*)d_in[1];
    const float* bu = (const float*)d_in[2];
    const float* ba = (const float*)d_in[3];
    float* out = (float*)d_out;

    const int batch = in_sizes[0] / 136;

    float *o1 = nullptr, *o2 = nullptr, *o3 = nullptr, *o4 = nullptr;
    if ((long long)out_size == (long long)batch * 136) {
        // only the final 'out' tensor
        o4 = out;
    } else {
        // flattened 4-tuple: p_out_p | a_out_p | out_p | out
        o1 = out;
        o2 = o1 + (long long)batch * 128;
        o3 = o2 + (long long)batch * 8;
        o4 = o3 + (long long)batch * 136;
    }

    const int grid = (batch + 7) / 8;
    caps_kernel<<<grid, 256>>>(x, w, bu, ba, o1, o2, o3, o4, batch);
}

// round 2
// speedup vs baseline: 1.0727x; 1.0727x over previous
#include <cuda_runtime.h>

// ConvCaps EM-routing: one warp per batch element.
// lane = hh*8 + c  (c = output capsule 0..7, hh = pose-row 0..3; lane owns h = hh*4+j, j=0..3)
// B (input capsule, 8) lives in registers. j-dimension packed 2-wide in f32x2.
// Reductions: over C -> shfl.bfly xor {1,2,4}; over h -> xor {8,16}; over B -> register loop.

#define FULLMASK 0xffffffffu
#define EPSF     1e-8f
#define HALF_LN2PI 0.9189385332046727f  // 0.5*ln(2*pi)

typedef unsigned long long u64;

__device__ __forceinline__ u64 pk2(float lo, float hi) {
    u64 r; asm("mov.b64 %0, {%1, %2};" : "=l"(r) : "f"(lo), "f"(hi)); return r;
}
__device__ __forceinline__ float2 up2(u64 v) {
    float2 f; asm("mov.b64 {%0, %1}, %2;" : "=f"(f.x), "=f"(f.y) : "l"(v)); return f;
}
__device__ __forceinline__ u64 ffma2(u64 a, u64 b, u64 c) {
    u64 d; asm("fma.rn.f32x2 %0, %1, %2, %3;" : "=l"(d) : "l"(a), "l"(b), "l"(c)); return d;
}
__device__ __forceinline__ u64 fadd2(u64 a, u64 b) {
    u64 d; asm("add.rn.f32x2 %0, %1, %2;" : "=l"(d) : "l"(a), "l"(b)); return d;
}
__device__ __forceinline__ u64 fmul2(u64 a, u64 b) {
    u64 d; asm("mul.rn.f32x2 %0, %1, %2;" : "=l"(d) : "l"(a), "l"(b)); return d;
}

static __global__ __launch_bounds__(256, 3)
void caps_kernel(const float* __restrict__ x,
                 const float* __restrict__ wts,
                 const float* __restrict__ bu_g,
                 const float* __restrict__ ba_g,
                 float* __restrict__ o1,   // p_out_p  [b][8][16]   (may be null)
                 float* __restrict__ o2,   // a_out_p  [b][8][1]    (may be null)
                 float* __restrict__ o3,   // out_p    [b][8][17]   (may be null)
                 float* __restrict__ o4,   // out      [b][136]     (may be null)
                 int batch)
{
    // weights transposed: w[B][c][k][j] -> w_s[(((B*4+k)*8+c)*4)+j]  (float4 per (B,k,c))
    __shared__ __align__(16) float w_s[1024];
    __shared__ float bu_s[8];
    __shared__ float ba_s[8];
    __shared__ __align__(16) float xb[8][136];

    const int tid  = threadIdx.x;
    const int warp = tid >> 5;
    const int lane = tid & 31;
    const int c    = lane & 7;
    const int hh   = lane >> 3;

    #pragma unroll
    for (int t = 0; t < 4; ++t) {
        int e = tid + t * 256;
        int B = e >> 7, cc = (e >> 4) & 7, k = (e >> 2) & 3, j = e & 3;
        w_s[((B * 4 + k) * 8 + cc) * 4 + j] = wts[e];
    }
    if (tid < 8) { bu_s[tid] = bu_g[tid]; ba_s[tid] = ba_g[tid]; }

    const long long b = (long long)blockIdx.x * 8 + warp;
    const bool valid = (b < (long long)batch);
    if (valid) {
        const float* xg = x + b * 136;
        #pragma unroll
        for (int t = 0; t < 4; ++t) xb[warp][lane + 32 * t] = xg[lane + 32 * t];
        if (lane < 8) xb[warp][128 + lane] = xg[128 + lane];
    }
    __syncthreads();

    const float* xw = xb[warp];

    // votes: v[B][c][h], h = hh*4+j.  v = sum_k p[hh][k] * W[B][c][k][j]
    // packed: v01 = (j=0,1), v23 = (j=2,3)
    u64 v01[8], v23[8];
    const float4* w4 = reinterpret_cast<const float4*>(w_s);
    #pragma unroll
    for (int B = 0; B < 8; ++B) {
        const float4 p = *reinterpret_cast<const float4*>(xw + B * 16 + hh * 4);
        const u64 q0 = pk2(p.x, p.x);
        const u64 q1 = pk2(p.y, p.y);
        const u64 q2 = pk2(p.z, p.z);
        const u64 q3 = pk2(p.w, p.w);
        const float4* wB = w4 + B * 32 + c;   // element k at wB[k*8]
        const float4 w0 = wB[0];
        const float4 w1 = wB[8];
        const float4 w2 = wB[16];
        const float4 w3 = wB[24];
        u64 a01 = fmul2(q0, pk2(w0.x, w0.y));
        a01 = ffma2(q1, pk2(w1.x, w1.y), a01);
        a01 = ffma2(q2, pk2(w2.x, w2.y), a01);
        a01 = ffma2(q3, pk2(w3.x, w3.y), a01);
        u64 a23 = fmul2(q0, pk2(w0.z, w0.w));
        a23 = ffma2(q1, pk2(w1.z, w1.w), a23);
        a23 = ffma2(q2, pk2(w2.z, w2.w), a23);
        a23 = ffma2(q3, pk2(w3.z, w3.w), a23);
        v01[B] = a01;
        v23[B] = a23;
    }

    const float bu = bu_s[c];
    const float ba = ba_s[c];
    const u64 NEG1 = pk2(-1.f, -1.f);
    const u64 EPS2 = pk2(EPSF, EPSF);

    float r[8];
    #pragma unroll
    for (int B = 0; B < 8; ++B) r[B] = 0.125f;

    u64 mu01 = 0, mu23 = 0;
    float a_out = 0.f;

    #pragma unroll
    for (int it = 0; it < 3; ++it) {
        // rr = r*a_in ; normalize over C ; rrn = pre-invrs coeff
        float rrn[8];
        float r_sum = 0.f;
        #pragma unroll
        for (int B = 0; B < 8; ++B) {
            float rr = r[B] * xw[128 + B];
            float d = rr;
            d += __shfl_xor_sync(FULLMASK, d, 1);
            d += __shfl_xor_sync(FULLMASK, d, 2);
            d += __shfl_xor_sync(FULLMASK, d, 4);
            float rn = rr * __fdividef(1.f, d + EPSF);
            rrn[B] = rn;
            r_sum += rn;
        }
        const float invrs = __fdividef(1.f, r_sum + EPSF);
        const u64 iv2 = pk2(invrs, invrs);

        // mu = invrs * sum_B rrn*v
        u64 m01 = 0, m23 = 0;
        #pragma unroll
        for (int B = 0; B < 8; ++B) {
            const u64 cb = pk2(rrn[B], rrn[B]);
            m01 = ffma2(cb, v01[B], m01);
            m23 = ffma2(cb, v23[B], m23);
        }
        mu01 = fmul2(m01, iv2);
        mu23 = fmul2(m23, iv2);

        // sigma^2 = invrs * sum_B rrn*(v-mu)^2 + eps
        const u64 n01 = fmul2(mu01, NEG1);
        const u64 n23 = fmul2(mu23, NEG1);
        u64 s01 = 0, s23 = 0;
        #pragma unroll
        for (int B = 0; B < 8; ++B) {
            const u64 cb = pk2(rrn[B], rrn[B]);
            u64 d01 = fadd2(v01[B], n01);
            u64 d23 = fadd2(v23[B], n23);
            s01 = ffma2(fmul2(cb, d01), d01, s01);
            s23 = ffma2(fmul2(cb, d23), d23, s23);
        }
        const u64 sg01 = ffma2(s01, iv2, EPS2);
        const u64 sg23 = ffma2(s23, iv2, EPS2);
        const float2 sA = up2(sg01);
        const float2 sB = up2(sg23);

        const float l0 = __logf(sA.x), l1 = __logf(sA.y);
        const float l2 = __logf(sB.x), l3 = __logf(sB.y);
        float Hs = 0.5f * ((l0 + l1) + (l2 + l3));
        Hs += __shfl_xor_sync(FULLMASK, Hs, 8);
        Hs += __shfl_xor_sync(FULLMASK, Hs, 16);

        const float cost = r_sum * (16.f * bu + Hs);
        const float z  = 1e-3f * (ba - cost);
        const float ez = __expf(-z);
        a_out = __fdividef(1.f, 1.f + ez);

        if (it < 2) {
            const float la = -__logf(1.f + ez);          // log(sigmoid(z))
            const float Kc = la - Hs - 16.f * HALF_LN2PI;
            const float i0 = __fdividef(0.5f, sA.x);
            const float i1 = __fdividef(0.5f, sA.y);
            const float i2 = __fdividef(0.5f, sB.x);
            const float i3 = __fdividef(0.5f, sB.y);
            const u64 is01 = pk2(i0, i1);
            const u64 is23 = pk2(i2, i3);

            #pragma unroll
            for (int B = 0; B < 8; ++B) {
                u64 d01 = fadd2(v01[B], n01);
                u64 d23 = fadd2(v23[B], n23);
                u64 t2 = fmul2(fmul2(d01, is01), d01);
                t2 = ffma2(fmul2(d23, is23), d23, t2);
                const float2 tp = up2(t2);
                float t = tp.x + tp.y;
                t += __shfl_xor_sync(FULLMASK, t, 8);
                t += __shfl_xor_sync(FULLMASK, t, 16);
                const float ln = Kc - t;
                // softmax over C (fused, no lnap array)
                float m = ln;
                m = fmaxf(m, __shfl_xor_sync(FULLMASK, m, 1));
                m = fmaxf(m, __shfl_xor_sync(FULLMASK, m, 2));
                m = fmaxf(m, __shfl_xor_sync(FULLMASK, m, 4));
                const float e = __expf(ln - m);
                float s = e;
                s += __shfl_xor_sync(FULLMASK, s, 1);
                s += __shfl_xor_sync(FULLMASK, s, 2);
                s += __shfl_xor_sync(FULLMASK, s, 4);
                r[B] = e * __fdividef(1.f, s);
            }
        }
    }

    if (!valid) return;

    const float2 mA = up2(mu01);
    const float2 mB = up2(mu23);
    const float4 m4 = make_float4(mA.x, mA.y, mB.x, mB.y);

    if (o1) {   // p_out_p [b][c][16]
        *reinterpret_cast<float4*>(o1 + b * 128 + c * 16 + hh * 4) = m4;
    }
    if (o2 && hh == 0) {   // a_out_p [b][c]
        o2[b * 8 + c] = a_out;
    }
    if (o3) {   // out_p [b][c][17]
        float* p = o3 + b * 136 + c * 17 + hh * 4;
        p[0] = m4.x; p[1] = m4.y; p[2] = m4.z; p[3] = m4.w;
        if (hh == 0) o3[b * 136 + c * 17 + 16] = a_out;
    }
    if (o4) {   // out [b][136] : 128 mu then 8 a_out
        *reinterpret_cast<float4*>(o4 + b * 136 + c * 16 + hh * 4) = m4;
        if (hh == 0) o4[b * 136 + 128 + c] = a_out;
    }
}

extern "C" void kernel_launch(void* const* d_in, const int* in_sizes, int n_in,
                              void* d_out, int out_size)
{
    const float* x  = (const float*)d_in[0];
    const float* w  = (const float*)d_in[1];
    const float* bu = (const float*)d_in[2];
    const float* ba = (const float*)d_in[3];
    float* out = (float*)d_out;

    const int batch = in_sizes[0] / 136;

    float *o1 = nullptr, *o2 = nullptr, *o3 = nullptr, *o4 = nullptr;
    if ((long long)out_size == (long long)batch * 136) {
        o4 = out;
    } else {
        o1 = out;
        o2 = o1 + (long long)batch * 128;
        o3 = o2 + (long long)batch * 8;
        o4 = o3 + (long long)batch * 136;
    }

    const int grid = (batch + 7) / 8;
    caps_kernel<<<grid, 256>>>(x, w, bu, ba, o1, o2, o3, o4, batch);
}

// round 3
// speedup vs baseline: 1.2086x; 1.1267x over previous
#include <cuda_runtime.h>

// ConvCaps EM-routing: one warp per batch element.
// lane = hh*8 + c  (c = output capsule 0..7, hh = pose-row 0..3; lane owns h = hh*4+j)
// B (input capsule, 8) lives in registers. j-dimension packed 2-wide in f32x2.
// Key identity: sum_C r == 1 (uniform init / softmax output), so the per-B
// C-normalization collapses to rrn[B] = r[B] * a/(a+eps)  -- no shuffles.

#define FULLMASK 0xffffffffu
#define EPSF     1e-8f
#define HALF_LN2PI 0.9189385332046727f  // 0.5*ln(2*pi)

typedef unsigned long long u64;

__device__ __forceinline__ u64 pk2(float lo, float hi) {
    u64 r; asm("mov.b64 %0, {%1, %2};" : "=l"(r) : "f"(lo), "f"(hi)); return r;
}
__device__ __forceinline__ float2 up2(u64 v) {
    float2 f; asm("mov.b64 {%0, %1}, %2;" : "=f"(f.x), "=f"(f.y) : "l"(v)); return f;
}
__device__ __forceinline__ u64 ffma2(u64 a, u64 b, u64 c) {
    u64 d; asm("fma.rn.f32x2 %0, %1, %2, %3;" : "=l"(d) : "l"(a), "l"(b), "l"(c)); return d;
}
__device__ __forceinline__ u64 fadd2(u64 a, u64 b) {
    u64 d; asm("add.rn.f32x2 %0, %1, %2;" : "=l"(d) : "l"(a), "l"(b)); return d;
}
__device__ __forceinline__ u64 fmul2(u64 a, u64 b) {
    u64 d; asm("mul.rn.f32x2 %0, %1, %2;" : "=l"(d) : "l"(a), "l"(b)); return d;
}

static __global__ __launch_bounds__(256, 3)
void caps_kernel(const float* __restrict__ x,
                 const float* __restrict__ wts,
                 const float* __restrict__ bu_g,
                 const float* __restrict__ ba_g,
                 float* __restrict__ o1,   // p_out_p  [b][8][16]   (may be null)
                 float* __restrict__ o2,   // a_out_p  [b][8][1]    (may be null)
                 float* __restrict__ o3,   // out_p    [b][8][17]   (may be null)
                 float* __restrict__ o4,   // out      [b][136]     (may be null)
                 int batch)
{
    // weights transposed: w[B][c][k][j] -> w_s[(((B*4+k)*8+c)*4)+j]  (float4 per (B,k,c))
    __shared__ __align__(16) float w_s[1024];
    __shared__ float bu_s[8];
    __shared__ float ba_s[8];

    const int tid  = threadIdx.x;
    const int warp = tid >> 5;
    const int lane = tid & 31;
    const int c    = lane & 7;
    const int hh   = lane >> 3;

    #pragma unroll
    for (int t = 0; t < 4; ++t) {
        int e = tid + t * 256;
        int B = e >> 7, cc = (e >> 4) & 7, k = (e >> 2) & 3, j = e & 3;
        w_s[((B * 4 + k) * 8 + cc) * 4 + j] = wts[e];
    }
    if (tid < 8) { bu_s[tid] = bu_g[tid]; ba_s[tid] = ba_g[tid]; }

    long long b = (long long)blockIdx.x * 8 + warp;
    if (b >= (long long)batch) b = (long long)batch - 1;   // clamp: redundant compute, same stores
    const float* xg = x + b * 136;

    __syncthreads();

    // af[B] = a_in/(a_in+eps); assumes sum_C r == 1 (exact for init & softmax output)
    float af[8];
    #pragma unroll
    for (int B = 0; B < 8; ++B) {
        const float a = __ldg(xg + 128 + B);
        af[B] = a * __fdividef(1.f, a + EPSF);
    }

    // votes: v[B][c][h], h = hh*4+j.  v = sum_k p[hh][k] * W[B][c][k][j]
    u64 v01[8], v23[8];
    const float4* w4 = reinterpret_cast<const float4*>(w_s);
    #pragma unroll
    for (int B = 0; B < 8; ++B) {
        const float4 p = __ldg(reinterpret_cast<const float4*>(xg + B * 16 + hh * 4));
        const u64 q0 = pk2(p.x, p.x);
        const u64 q1 = pk2(p.y, p.y);
        const u64 q2 = pk2(p.z, p.z);
        const u64 q3 = pk2(p.w, p.w);
        const float4* wB = w4 + B * 32 + c;   // element k at wB[k*8]
        const float4 w0 = wB[0];
        const float4 w1 = wB[8];
        const float4 w2 = wB[16];
        const float4 w3 = wB[24];
        u64 a01 = fmul2(q0, pk2(w0.x, w0.y));
        a01 = ffma2(q1, pk2(w1.x, w1.y), a01);
        a01 = ffma2(q2, pk2(w2.x, w2.y), a01);
        a01 = ffma2(q3, pk2(w3.x, w3.y), a01);
        u64 a23 = fmul2(q0, pk2(w0.z, w0.w));
        a23 = ffma2(q1, pk2(w1.z, w1.w), a23);
        a23 = ffma2(q2, pk2(w2.z, w2.w), a23);
        a23 = ffma2(q3, pk2(w3.z, w3.w), a23);
        v01[B] = a01;
        v23[B] = a23;
    }

    const float bu = bu_s[c];
    const float ba = ba_s[c];
    const u64 NEG1 = pk2(-1.f, -1.f);
    const u64 EPS2 = pk2(EPSF, EPSF);

    // rrn = r * af ; iter 0 has r = 1/8 uniform
    float rrn[8];
    #pragma unroll
    for (int B = 0; B < 8; ++B) rrn[B] = 0.125f * af[B];

    u64 mu01 = 0, mu23 = 0;
    float a_out = 0.f;

    #pragma unroll
    for (int it = 0; it < 3; ++it) {
        float r_sum = 0.f;
        #pragma unroll
        for (int B = 0; B < 8; ++B) r_sum += rrn[B];

        const float invrs = __fdividef(1.f, r_sum + EPSF);
        const u64 iv2 = pk2(invrs, invrs);

        // mu = invrs * sum_B rrn*v
        u64 m01 = 0, m23 = 0;
        #pragma unroll
        for (int B = 0; B < 8; ++B) {
            const u64 cb = pk2(rrn[B], rrn[B]);
            m01 = ffma2(cb, v01[B], m01);
            m23 = ffma2(cb, v23[B], m23);
        }
        mu01 = fmul2(m01, iv2);
        mu23 = fmul2(m23, iv2);

        // sigma^2 = invrs * sum_B rrn*(v-mu)^2 + eps
        const u64 n01 = fmul2(mu01, NEG1);
        const u64 n23 = fmul2(mu23, NEG1);
        u64 s01 = 0, s23 = 0;
        #pragma unroll
        for (int B = 0; B < 8; ++B) {
            const u64 cb = pk2(rrn[B], rrn[B]);
            u64 d01 = fadd2(v01[B], n01);
            u64 d23 = fadd2(v23[B], n23);
            s01 = ffma2(fmul2(cb, d01), d01, s01);
            s23 = ffma2(fmul2(cb, d23), d23, s23);
        }
        const u64 sg01 = ffma2(s01, iv2, EPS2);
        const u64 sg23 = ffma2(s23, iv2, EPS2);
        const float2 sA = up2(sg01);
        const float2 sB = up2(sg23);

        const float l0 = __logf(sA.x), l1 = __logf(sA.y);
        const float l2 = __logf(sB.x), l3 = __logf(sB.y);
        float Hs = 0.5f * ((l0 + l1) + (l2 + l3));
        Hs += __shfl_xor_sync(FULLMASK, Hs, 8);
        Hs += __shfl_xor_sync(FULLMASK, Hs, 16);

        const float cost = r_sum * (16.f * bu + Hs);
        const float z  = 1e-3f * (ba - cost);
        const float ez = __expf(-z);
        a_out = __fdividef(1.f, 1.f + ez);

        if (it < 2) {
            const float la = -__logf(1.f + ez);          // log(sigmoid(z))
            const float Kc = la - Hs - 16.f * HALF_LN2PI;
            const float i0 = __fdividef(0.5f, sA.x);
            const float i1 = __fdividef(0.5f, sA.y);
            const float i2 = __fdividef(0.5f, sB.x);
            const float i3 = __fdividef(0.5f, sB.y);
            const u64 is01 = pk2(i0, i1);
            const u64 is23 = pk2(i2, i3);

            #pragma unroll
            for (int B = 0; B < 8; ++B) {
                u64 d01 = fadd2(v01[B], n01);
                u64 d23 = fadd2(v23[B], n23);
                u64 t2 = fmul2(fmul2(d01, is01), d01);
                t2 = ffma2(fmul2(d23, is23), d23, t2);
                const float2 tp = up2(t2);
                float t = tp.x + tp.y;
                t += __shfl_xor_sync(FULLMASK, t, 8);
                t += __shfl_xor_sync(FULLMASK, t, 16);
                const float ln = Kc - t;
                // softmax over C, fused; next iter's rrn folded in
                float m = ln;
                m = fmaxf(m, __shfl_xor_sync(FULLMASK, m, 1));
                m = fmaxf(m, __shfl_xor_sync(FULLMASK, m, 2));
                m = fmaxf(m, __shfl_xor_sync(FULLMASK, m, 4));
                const float e = __expf(ln - m);
                float s = e;
                s += __shfl_xor_sync(FULLMASK, s, 1);
                s += __shfl_xor_sync(FULLMASK, s, 2);
                s += __shfl_xor_sync(FULLMASK, s, 4);
                rrn[B] = e * __fdividef(1.f, s) * af[B];
            }
        }
    }

    const float2 mA = up2(mu01);
    const float2 mB = up2(mu23);
    const float4 m4 = make_float4(mA.x, mA.y, mB.x, mB.y);

    if (o1) {   // p_out_p [b][c][16]
        *reinterpret_cast<float4*>(o1 + b * 128 + c * 16 + hh * 4) = m4;
    }
    if (o2 && hh == 0) {   // a_out_p [b][c]
        o2[b * 8 + c] = a_out;
    }
    if (o3) {   // out_p [b][c][17]
        float* p = o3 + b * 136 + c * 17 + hh * 4;
        p[0] = m4.x; p[1] = m4.y; p[2] = m4.z; p[3] = m4.w;
        if (hh == 0) o3[b * 136 + c * 17 + 16] = a_out;
    }
    if (o4) {   // out [b][136] : 128 mu then 8 a_out
        *reinterpret_cast<float4*>(o4 + b * 136 + c * 16 + hh * 4) = m4;
        if (hh == 0) o4[b * 136 + 128 + c] = a_out;
    }
}

extern "C" void kernel_launch(void* const* d_in, const int* in_sizes, int n_in,
                              void* d_out, int out_size)
{
    const float* x  = (const float*)d_in[0];
    const float* w  = (const float*)d_in[1];
    const float* bu = (const float*)d_in[2];
    const float* ba = (const float*)d_in[3];
    float* out = (float*)d_out;

    const int batch = in_sizes[0] / 136;

    float *o1 = nullptr, *o2 = nullptr, *o3 = nullptr, *o4 = nullptr;
    if ((long long)out_size == (long long)batch * 136) {
        o4 = out;
    } else {
        o1 = out;
        o2 = o1 + (long long)batch * 128;
        o3 = o2 + (long long)batch * 8;
        o4 = o3 + (long long)batch * 136;
    }

    const int grid = (batch + 7) / 8;
    caps_kernel<<<grid, 256>>>(x, w, bu, ba, o1, o2, o3, o4, batch);
}

// round 4
// speedup vs baseline: 1.4162x; 1.1717x over previous
#include <cuda_runtime.h>

// ConvCaps EM-routing: one warp per batch element.
// lane = hh*8 + c (c = output capsule 0..7, hh = group 0..3; lane owns h = hh*4+j).
// Per-B state stored in RELATIVE slot order: slot k <-> input capsule group (hh^k),
// B(k,u) = 2*(hh^k)+u. XOR-butterfly reduce-scatter / all-gather are then select-free,
// and each hh group runs the C-softmax for only its own 2 B's (4x dedup of shuffles).

#define FULLMASK 0xffffffffu
#define EPSF     1e-8f
#define HALF_LN2PI 0.9189385332046727f  // 0.5*ln(2*pi)

typedef unsigned long long u64;

__device__ __forceinline__ u64 pk2(float lo, float hi) {
    u64 r; asm("mov.b64 %0, {%1, %2};" : "=l"(r) : "f"(lo), "f"(hi)); return r;
}
__device__ __forceinline__ float2 up2(u64 v) {
    float2 f; asm("mov.b64 {%0, %1}, %2;" : "=f"(f.x), "=f"(f.y) : "l"(v)); return f;
}
__device__ __forceinline__ u64 ffma2(u64 a, u64 b, u64 c) {
    u64 d; asm("fma.rn.f32x2 %0, %1, %2, %3;" : "=l"(d) : "l"(a), "l"(b), "l"(c)); return d;
}
__device__ __forceinline__ u64 fadd2(u64 a, u64 b) {
    u64 d; asm("add.rn.f32x2 %0, %1, %2;" : "=l"(d) : "l"(a), "l"(b)); return d;
}
__device__ __forceinline__ u64 fmul2(u64 a, u64 b) {
    u64 d; asm("mul.rn.f32x2 %0, %1, %2;" : "=l"(d) : "l"(a), "l"(b)); return d;
}

static __global__ __launch_bounds__(256, 3)
void caps_kernel(const float* __restrict__ x,
                 const float* __restrict__ wts,
                 const float* __restrict__ bu_g,
                 const float* __restrict__ ba_g,
                 float* __restrict__ o1,   // p_out_p  [b][8][16]
                 float* __restrict__ o2,   // a_out_p  [b][8][1]
                 float* __restrict__ o3,   // out_p    [b][8][17]
                 float* __restrict__ o4,   // out      [b][136]
                 int batch)
{
    // weights transposed: w[B][c][k][j] -> w_s[(((B*4+k)*8+c)*4)+j]  (float4 per (B,k,c))
    __shared__ __align__(16) float w_s[1024];
    __shared__ float bu_s[8];
    __shared__ float ba_s[8];

    const int tid  = threadIdx.x;
    const int warp = tid >> 5;
    const int lane = tid & 31;
    const int c    = lane & 7;
    const int hh   = lane >> 3;

    #pragma unroll
    for (int t = 0; t < 4; ++t) {
        int e = tid + t * 256;
        int B = e >> 7, cc = (e >> 4) & 7, k = (e >> 2) & 3, j = e & 3;
        w_s[((B * 4 + k) * 8 + cc) * 4 + j] = wts[e];
    }
    if (tid < 8) { bu_s[tid] = bu_g[tid]; ba_s[tid] = ba_g[tid]; }

    long long b = (long long)blockIdx.x * 8 + warp;
    if (b >= (long long)batch) b = (long long)batch - 1;   // clamp: redundant compute, same stores
    const float* xg = x + b * 136;

    __syncthreads();

    // -------- votes + activations, stored in relative slot order --------
    // slot (k,u): input capsule B = 2*(hh^k)+u
    u64 v01[8], v23[8];     // [k*2+u]
    float af[8];            // af = a/(a+eps)  (sum_C r == 1 identity)
    const float4* w4 = reinterpret_cast<const float4*>(w_s);
    #pragma unroll
    for (int k = 0; k < 4; ++k) {
        const int g = hh ^ k;
        #pragma unroll
        for (int u = 0; u < 2; ++u) {
            const int B = 2 * g + u;
            const int s = k * 2 + u;
            const float a = __ldg(xg + 128 + B);
            af[s] = a * __fdividef(1.f, a + EPSF);

            const float4 p = __ldg(reinterpret_cast<const float4*>(xg + B * 16 + hh * 4));
            const u64 q0 = pk2(p.x, p.x);
            const u64 q1 = pk2(p.y, p.y);
            const u64 q2 = pk2(p.z, p.z);
            const u64 q3 = pk2(p.w, p.w);
            const float4* wB = w4 + B * 32 + c;   // element kk at wB[kk*8]
            const float4 w0 = wB[0];
            const float4 w1 = wB[8];
            const float4 w2 = wB[16];
            const float4 w3 = wB[24];
            u64 a01 = fmul2(q0, pk2(w0.x, w0.y));
            a01 = ffma2(q1, pk2(w1.x, w1.y), a01);
            a01 = ffma2(q2, pk2(w2.x, w2.y), a01);
            a01 = ffma2(q3, pk2(w3.x, w3.y), a01);
            u64 a23 = fmul2(q0, pk2(w0.z, w0.w));
            a23 = ffma2(q1, pk2(w1.z, w1.w), a23);
            a23 = ffma2(q2, pk2(w2.z, w2.w), a23);
            a23 = ffma2(q3, pk2(w3.z, w3.w), a23);
            v01[s] = a01;
            v23[s] = a23;
        }
    }

    const float bu = bu_s[c];
    const float ba = ba_s[c];
    const u64 NEG1 = pk2(-1.f, -1.f);
    const u64 EPS2 = pk2(EPSF, EPSF);

    float rrn[8];
    #pragma unroll
    for (int s = 0; s < 8; ++s) rrn[s] = 0.125f * af[s];

    u64 mu01 = 0, mu23 = 0;
    float a_out = 0.f;

    #pragma unroll
    for (int it = 0; it < 3; ++it) {
        float r_sum = 0.f;
        #pragma unroll
        for (int s = 0; s < 8; ++s) r_sum += rrn[s];

        const float invrs = __fdividef(1.f, r_sum + EPSF);
        const u64 iv2 = pk2(invrs, invrs);

        // mu = invrs * sum rrn*v
        u64 m01 = 0, m23 = 0;
        #pragma unroll
        for (int s = 0; s < 8; ++s) {
            const u64 cb = pk2(rrn[s], rrn[s]);
            m01 = ffma2(cb, v01[s], m01);
            m23 = ffma2(cb, v23[s], m23);
        }
        mu01 = fmul2(m01, iv2);
        mu23 = fmul2(m23, iv2);

        // sigma^2 = invrs * sum rrn*(v-mu)^2 + eps
        const u64 n01 = fmul2(mu01, NEG1);
        const u64 n23 = fmul2(mu23, NEG1);
        u64 s01 = 0, s23 = 0;
        #pragma unroll
        for (int s = 0; s < 8; ++s) {
            const u64 cb = pk2(rrn[s], rrn[s]);
            u64 d01 = fadd2(v01[s], n01);
            u64 d23 = fadd2(v23[s], n23);
            s01 = ffma2(fmul2(cb, d01), d01, s01);
            s23 = ffma2(fmul2(cb, d23), d23, s23);
        }
        const u64 sg01 = ffma2(s01, iv2, EPS2);
        const u64 sg23 = ffma2(s23, iv2, EPS2);
        const float2 sA = up2(sg01);
        const float2 sB = up2(sg23);

        const float l0 = __logf(sA.x), l1 = __logf(sA.y);
        const float l2 = __logf(sB.x), l3 = __logf(sB.y);
        float Hs = 0.5f * ((l0 + l1) + (l2 + l3));
        Hs += __shfl_xor_sync(FULLMASK, Hs, 8);
        Hs += __shfl_xor_sync(FULLMASK, Hs, 16);

        const float cost = r_sum * (16.f * bu + Hs);
        const float z  = 1e-3f * (ba - cost);
        const float ez = __expf(-z);
        a_out = __fdividef(1.f, 1.f + ez);

        if (it < 2) {
            const float la = -__logf(1.f + ez);          // log(sigmoid(z))
            const float Kc = la - Hs - 16.f * HALF_LN2PI;
            const float i0 = __fdividef(0.5f, sA.x);
            const float i1 = __fdividef(0.5f, sA.y);
            const float i2 = __fdividef(0.5f, sB.x);
            const float i3 = __fdividef(0.5f, sB.y);
            const u64 is01 = pk2(i0, i1);
            const u64 is23 = pk2(i2, i3);

            // per-lane partial t for all 8 slots (own 4 h values)
            float tp[8];
            #pragma unroll
            for (int s = 0; s < 8; ++s) {
                u64 d01 = fadd2(v01[s], n01);
                u64 d23 = fadd2(v23[s], n23);
                u64 t2 = fmul2(fmul2(d01, is01), d01);
                t2 = ffma2(fmul2(d23, is23), d23, t2);
                const float2 t = up2(t2);
                tp[s] = t.x + t.y;
            }

            // reduce-scatter over hh (relative slots -> select-free):
            // round 1 (xor16): partner's slot 2+i is MY groups (hh, hh^1)
            float t2r[4];
            #pragma unroll
            for (int i = 0; i < 4; ++i)
                t2r[i] = tp[i] + __shfl_xor_sync(FULLMASK, tp[4 + i], 16);
            // round 2 (xor8): partner's slot 1 is MY group hh
            float tf[2];
            #pragma unroll
            for (int u = 0; u < 2; ++u)
                tf[u] = t2r[u] + __shfl_xor_sync(FULLMASK, t2r[2 + u], 8);

            // softmax over C for this group's 2 B's
            float rloc[2];
            #pragma unroll
            for (int u = 0; u < 2; ++u) {
                const float ln = Kc - tf[u];
                float m = ln;
                m = fmaxf(m, __shfl_xor_sync(FULLMASK, m, 1));
                m = fmaxf(m, __shfl_xor_sync(FULLMASK, m, 2));
                m = fmaxf(m, __shfl_xor_sync(FULLMASK, m, 4));
                const float e = __expf(ln - m);
                float ssum = e;
                ssum += __shfl_xor_sync(FULLMASK, ssum, 1);
                ssum += __shfl_xor_sync(FULLMASK, ssum, 2);
                ssum += __shfl_xor_sync(FULLMASK, ssum, 4);
                rloc[u] = e * __fdividef(1.f, ssum);
            }

            // all-gather r (relative slots): slot1 = xor8, slot2 = xor16, slot3 = xor16 of slot1
            float r1u[2], r2u[2], r3u[2];
            #pragma unroll
            for (int u = 0; u < 2; ++u) r1u[u] = __shfl_xor_sync(FULLMASK, rloc[u], 8);
            #pragma unroll
            for (int u = 0; u < 2; ++u) r2u[u] = __shfl_xor_sync(FULLMASK, rloc[u], 16);
            #pragma unroll
            for (int u = 0; u < 2; ++u) r3u[u] = __shfl_xor_sync(FULLMASK, r1u[u], 16);

            #pragma unroll
            for (int u = 0; u < 2; ++u) {
                rrn[0 + u] = rloc[u] * af[0 + u];
                rrn[2 + u] = r1u[u]  * af[2 + u];
                rrn[4 + u] = r2u[u]  * af[4 + u];
                rrn[6 + u] = r3u[u]  * af[6 + u];
            }
        }
    }

    const float2 mA = up2(mu01);
    const float2 mB = up2(mu23);
    const float4 m4 = make_float4(mA.x, mA.y, mB.x, mB.y);

    if (o1) {   // p_out_p [b][c][16]
        *reinterpret_cast<float4*>(o1 + b * 128 + c * 16 + hh * 4) = m4;
    }
    if (o2 && hh == 0) {   // a_out_p [b][c]
        o2[b * 8 + c] = a_out;
    }
    if (o3) {   // out_p [b][c][17]
        float* p = o3 + b * 136 + c * 17 + hh * 4;
        p[0] = m4.x; p[1] = m4.y; p[2] = m4.z; p[3] = m4.w;
        if (hh == 0) o3[b * 136 + c * 17 + 16] = a_out;
    }
    if (o4) {   // out [b][136] : 128 mu then 8 a_out
        *reinterpret_cast<float4*>(o4 + b * 136 + c * 16 + hh * 4) = m4;
        if (hh == 0) o4[b * 136 + 128 + c] = a_out;
    }
}

extern "C" void kernel_launch(void* const* d_in, const int* in_sizes, int n_in,
                              void* d_out, int out_size)
{
    const float* x  = (const float*)d_in[0];
    const float* w  = (const float*)d_in[1];
    const float* bu = (const float*)d_in[2];
    const float* ba = (const float*)d_in[3];
    float* out = (float*)d_out;

    const int batch = in_sizes[0] / 136;

    float *o1 = nullptr, *o2 = nullptr, *o3 = nullptr, *o4 = nullptr;
    if ((long long)out_size == (long long)batch * 136) {
        o4 = out;
    } else {
        o1 = out;
        o2 = o1 + (long long)batch * 128;
        o3 = o2 + (long long)batch * 8;
        o4 = o3 + (long long)batch * 136;
    }

    const int grid = (batch + 7) / 8;
    caps_kernel<<<grid, 256>>>(x, w, bu, ba, o1, o2, o3, o4, batch);
}

// round 5
// speedup vs baseline: 1.8288x; 1.2914x over previous
#include <cuda_runtime.h>

// ConvCaps EM-routing: HALF-warp (16 lanes) per batch element, 2 elements/warp.
// lane = e*16 + hh2*8 + c  (e = element half, hh2 in {0,1} owns pose rows 2*hh2, 2*hh2+1,
// c = output capsule). Weights are batch-independent -> each weight LDS serves 2 elements.
// Per-B state in RELATIVE slot order: slot s = k*4+u, input capsule B = 4*(hh2^k)+u, so
// xor8 butterflies are select-free. Softmax over C via xor{1,2,4} within c-octets.

#define FULLMASK 0xffffffffu
#define EPSF     1e-8f
#define HALF_LN2PI 0.9189385332046727f  // 0.5*ln(2*pi)

typedef unsigned long long u64;

__device__ __forceinline__ u64 pk2(float lo, float hi) {
    u64 r; asm("mov.b64 %0, {%1, %2};" : "=l"(r) : "f"(lo), "f"(hi)); return r;
}
__device__ __forceinline__ float2 up2(u64 v) {
    float2 f; asm("mov.b64 {%0, %1}, %2;" : "=f"(f.x), "=f"(f.y) : "l"(v)); return f;
}
__device__ __forceinline__ u64 ffma2(u64 a, u64 b, u64 c) {
    u64 d; asm("fma.rn.f32x2 %0, %1, %2, %3;" : "=l"(d) : "l"(a), "l"(b), "l"(c)); return d;
}
__device__ __forceinline__ u64 fadd2(u64 a, u64 b) {
    u64 d; asm("add.rn.f32x2 %0, %1, %2;" : "=l"(d) : "l"(a), "l"(b)); return d;
}
__device__ __forceinline__ u64 fmul2(u64 a, u64 b) {
    u64 d; asm("mul.rn.f32x2 %0, %1, %2;" : "=l"(d) : "l"(a), "l"(b)); return d;
}

static __global__ __launch_bounds__(256, 2)
void caps_kernel(const float* __restrict__ x,
                 const float* __restrict__ wts,
                 const float* __restrict__ bu_g,
                 const float* __restrict__ ba_g,
                 float* __restrict__ o1,   // p_out_p  [b][8][16]
                 float* __restrict__ o2,   // a_out_p  [b][8][1]
                 float* __restrict__ o3,   // out_p    [b][8][17]
                 float* __restrict__ o4,   // out      [b][136]
                 int batch)
{
    // weights transposed: w[B][c][k][j] -> w_s[(((B*4+k)*8+c)*4)+j]  (float4 per (B,k,c))
    __shared__ __align__(16) float w_s[1024];
    __shared__ float bu_s[8];
    __shared__ float ba_s[8];

    const int tid  = threadIdx.x;
    const int warp = tid >> 5;
    const int lane = tid & 31;
    const int e    = lane >> 4;
    const int c    = lane & 7;
    const int hh2  = (lane >> 3) & 1;

    #pragma unroll
    for (int t = 0; t < 4; ++t) {
        int ei = tid + t * 256;
        int B = ei >> 7, cc = (ei >> 4) & 7, k = (ei >> 2) & 3, j = ei & 3;
        w_s[((B * 4 + k) * 8 + cc) * 4 + j] = wts[ei];
    }
    if (tid < 8) { bu_s[tid] = bu_g[tid]; ba_s[tid] = ba_g[tid]; }

    long long b = (long long)blockIdx.x * 16 + warp * 2 + e;
    if (b >= (long long)batch) b = (long long)batch - 1;   // clamp: duplicate work, same stores
    const float* xg = x + b * 136;

    __syncthreads();

    // ---- activations: af = a/(a+eps)  (sum_C r == 1 identity). slot s=k*4+u -> B=4*(hh2^k)+u
    const float4 av0 = __ldg(reinterpret_cast<const float4*>(xg + 128)); // B 0..3
    const float4 av1 = __ldg(reinterpret_cast<const float4*>(xg + 132)); // B 4..7
    const float4 aown = hh2 ? av1 : av0;   // k=0 group
    const float4 aoth = hh2 ? av0 : av1;   // k=1 group
    float af[8];
    af[0] = aown.x * __fdividef(1.f, aown.x + EPSF);
    af[1] = aown.y * __fdividef(1.f, aown.y + EPSF);
    af[2] = aown.z * __fdividef(1.f, aown.z + EPSF);
    af[3] = aown.w * __fdividef(1.f, aown.w + EPSF);
    af[4] = aoth.x * __fdividef(1.f, aoth.x + EPSF);
    af[5] = aoth.y * __fdividef(1.f, aoth.y + EPSF);
    af[6] = aoth.z * __fdividef(1.f, aoth.z + EPSF);
    af[7] = aoth.w * __fdividef(1.f, aoth.w + EPSF);

    // ---- votes: lane owns pose rows i0=2*hh2, i1=2*hh2+1; 8 h values per slot.
    // vA* = row i0, vB* = row i1; *01 = (j0,j1), *23 = (j2,j3)
    u64 vA01[8], vA23[8], vB01[8], vB23[8];
    const float4* w4 = reinterpret_cast<const float4*>(w_s);
    const int i0 = 2 * hh2;
    #pragma unroll
    for (int k = 0; k < 2; ++k) {
        const int g = hh2 ^ k;
        #pragma unroll
        for (int u = 0; u < 4; ++u) {
            const int B = 4 * g + u;
            const int s = k * 4 + u;
            const float4 pA = __ldg(reinterpret_cast<const float4*>(xg + B * 16 + i0 * 4));
            const float4 pB = __ldg(reinterpret_cast<const float4*>(xg + B * 16 + i0 * 4 + 4));
            const float4* wB = w4 + B * 32 + c;
            const float4 w0 = wB[0];
            const float4 w1 = wB[8];
            const float4 w2 = wB[16];
            const float4 w3 = wB[24];
            const u64 wk0a = pk2(w0.x, w0.y), wk0b = pk2(w0.z, w0.w);
            const u64 wk1a = pk2(w1.x, w1.y), wk1b = pk2(w1.z, w1.w);
            const u64 wk2a = pk2(w2.x, w2.y), wk2b = pk2(w2.z, w2.w);
            const u64 wk3a = pk2(w3.x, w3.y), wk3b = pk2(w3.z, w3.w);

            u64 q0 = pk2(pA.x, pA.x), q1 = pk2(pA.y, pA.y);
            u64 q2 = pk2(pA.z, pA.z), q3 = pk2(pA.w, pA.w);
            u64 r01 = fmul2(q0, wk0a);
            r01 = ffma2(q1, wk1a, r01);
            r01 = ffma2(q2, wk2a, r01);
            r01 = ffma2(q3, wk3a, r01);
            u64 r23 = fmul2(q0, wk0b);
            r23 = ffma2(q1, wk1b, r23);
            r23 = ffma2(q2, wk2b, r23);
            r23 = ffma2(q3, wk3b, r23);
            vA01[s] = r01; vA23[s] = r23;

            q0 = pk2(pB.x, pB.x); q1 = pk2(pB.y, pB.y);
            q2 = pk2(pB.z, pB.z); q3 = pk2(pB.w, pB.w);
            r01 = fmul2(q0, wk0a);
            r01 = ffma2(q1, wk1a, r01);
            r01 = ffma2(q2, wk2a, r01);
            r01 = ffma2(q3, wk3a, r01);
            r23 = fmul2(q0, wk0b);
            r23 = ffma2(q1, wk1b, r23);
            r23 = ffma2(q2, wk2b, r23);
            r23 = ffma2(q3, wk3b, r23);
            vB01[s] = r01; vB23[s] = r23;
        }
    }

    const float bu = bu_s[c];
    const float ba = ba_s[c];
    const u64 NEG1 = pk2(-1.f, -1.f);
    const u64 EPS2 = pk2(EPSF, EPSF);

    float rrn[8];
    #pragma unroll
    for (int s = 0; s < 8; ++s) rrn[s] = 0.125f * af[s];

    u64 muA01 = 0, muA23 = 0, muB01 = 0, muB23 = 0;
    float a_out = 0.f;

    #pragma unroll
    for (int it = 0; it < 3; ++it) {
        float r_sum = 0.f;
        #pragma unroll
        for (int s = 0; s < 8; ++s) r_sum += rrn[s];

        const float invrs = __fdividef(1.f, r_sum + EPSF);
        const u64 iv2 = pk2(invrs, invrs);

        // mu = invrs * sum rrn*v
        u64 mA01 = 0, mA23 = 0, mB01 = 0, mB23 = 0;
        #pragma unroll
        for (int s = 0; s < 8; ++s) {
            const u64 cb = pk2(rrn[s], rrn[s]);
            mA01 = ffma2(cb, vA01[s], mA01);
            mA23 = ffma2(cb, vA23[s], mA23);
            mB01 = ffma2(cb, vB01[s], mB01);
            mB23 = ffma2(cb, vB23[s], mB23);
        }
        muA01 = fmul2(mA01, iv2);
        muA23 = fmul2(mA23, iv2);
        muB01 = fmul2(mB01, iv2);
        muB23 = fmul2(mB23, iv2);

        // sigma^2 = invrs * sum rrn*(v-mu)^2 + eps
        const u64 nA01 = fmul2(muA01, NEG1), nA23 = fmul2(muA23, NEG1);
        const u64 nB01 = fmul2(muB01, NEG1), nB23 = fmul2(muB23, NEG1);
        u64 sA01 = 0, sA23 = 0, sB01 = 0, sB23 = 0;
        #pragma unroll
        for (int s = 0; s < 8; ++s) {
            const u64 cb = pk2(rrn[s], rrn[s]);
            u64 d;
            d = fadd2(vA01[s], nA01); sA01 = ffma2(fmul2(cb, d), d, sA01);
            d = fadd2(vA23[s], nA23); sA23 = ffma2(fmul2(cb, d), d, sA23);
            d = fadd2(vB01[s], nB01); sB01 = ffma2(fmul2(cb, d), d, sB01);
            d = fadd2(vB23[s], nB23); sB23 = ffma2(fmul2(cb, d), d, sB23);
        }
        const u64 gA01 = ffma2(sA01, iv2, EPS2);
        const u64 gA23 = ffma2(sA23, iv2, EPS2);
        const u64 gB01 = ffma2(sB01, iv2, EPS2);
        const u64 gB23 = ffma2(sB23, iv2, EPS2);
        const float2 fA0 = up2(gA01), fA2 = up2(gA23);
        const float2 fB0 = up2(gB01), fB2 = up2(gB23);

        // pairwise-merged logs: sum_h log(sig) = sum of 4 pair logs (pair prod >= 1e-16, safe)
        const float lp0 = __logf(fA0.x * fA0.y);
        const float lp1 = __logf(fA2.x * fA2.y);
        const float lp2 = __logf(fB0.x * fB0.y);
        const float lp3 = __logf(fB2.x * fB2.y);
        float hpart = 0.5f * ((lp0 + lp1) + (lp2 + lp3));
        float Hs = hpart + __shfl_xor_sync(FULLMASK, hpart, 8);

        const float cost = r_sum * (16.f * bu + Hs);
        const float z  = 1e-3f * (ba - cost);
        const float ez = __expf(-z);
        a_out = __fdividef(1.f, 1.f + ez);

        if (it < 2) {
            const float la = -__logf(1.f + ez);          // log(sigmoid(z))
            const float Kc = la - Hs - 16.f * HALF_LN2PI;
            // is = 1/sig (0.5 factor folded into tp scale)
            const u64 iA01 = pk2(__fdividef(1.f, fA0.x), __fdividef(1.f, fA0.y));
            const u64 iA23 = pk2(__fdividef(1.f, fA2.x), __fdividef(1.f, fA2.y));
            const u64 iB01 = pk2(__fdividef(1.f, fB0.x), __fdividef(1.f, fB0.y));
            const u64 iB23 = pk2(__fdividef(1.f, fB2.x), __fdividef(1.f, fB2.y));

            float tp[8];
            #pragma unroll
            for (int s = 0; s < 8; ++s) {
                u64 d, t2;
                d = fadd2(vA01[s], nA01); t2 = fmul2(fmul2(d, iA01), d);
                d = fadd2(vA23[s], nA23); t2 = ffma2(fmul2(d, iA23), d, t2);
                d = fadd2(vB01[s], nB01); t2 = ffma2(fmul2(d, iB01), d, t2);
                d = fadd2(vB23[s], nB23); t2 = ffma2(fmul2(d, iB23), d, t2);
                const float2 tu = up2(t2);
                tp[s] = 0.5f * (tu.x + tu.y);
            }

            // reduce-scatter over hh2 (xor8): own group's 4 B's
            float tf[4];
            #pragma unroll
            for (int u = 0; u < 4; ++u)
                tf[u] = tp[u] + __shfl_xor_sync(FULLMASK, tp[4 + u], 8);

            // softmax over C for this group's 4 B's
            float rloc[4];
            #pragma unroll
            for (int u = 0; u < 4; ++u) {
                const float ln = Kc - tf[u];
                float m = ln;
                m = fmaxf(m, __shfl_xor_sync(FULLMASK, m, 1));
                m = fmaxf(m, __shfl_xor_sync(FULLMASK, m, 2));
                m = fmaxf(m, __shfl_xor_sync(FULLMASK, m, 4));
                const float ex = __expf(ln - m);
                float ssum = ex;
                ssum += __shfl_xor_sync(FULLMASK, ssum, 1);
                ssum += __shfl_xor_sync(FULLMASK, ssum, 2);
                ssum += __shfl_xor_sync(FULLMASK, ssum, 4);
                rloc[u] = ex * __fdividef(1.f, ssum);
            }

            // all-gather other group's r (xor8)
            #pragma unroll
            for (int u = 0; u < 4; ++u) {
                rrn[u]     = rloc[u] * af[u];
                rrn[4 + u] = __shfl_xor_sync(FULLMASK, rloc[u], 8) * af[4 + u];
            }
        }
    }

    const float2 mA0 = up2(muA01), mA2 = up2(muA23);
    const float2 mB0 = up2(muB01), mB2 = up2(muB23);
    const float4 m4A = make_float4(mA0.x, mA0.y, mA2.x, mA2.y);   // row i0
    const float4 m4B = make_float4(mB0.x, mB0.y, mB2.x, mB2.y);   // row i0+1

    if (o1) {   // p_out_p [b][c][16]
        *reinterpret_cast<float4*>(o1 + b * 128 + c * 16 + i0 * 4)     = m4A;
        *reinterpret_cast<float4*>(o1 + b * 128 + c * 16 + i0 * 4 + 4) = m4B;
    }
    if (o2 && hh2 == 0) {   // a_out_p [b][c]
        o2[b * 8 + c] = a_out;
    }
    if (o3) {   // out_p [b][c][17]
        float* p = o3 + b * 136 + c * 17 + i0 * 4;
        p[0] = m4A.x; p[1] = m4A.y; p[2] = m4A.z; p[3] = m4A.w;
        p[4] = m4B.x; p[5] = m4B.y; p[6] = m4B.z; p[7] = m4B.w;
        if (hh2 == 0) o3[b * 136 + c * 17 + 16] = a_out;
    }
    if (o4) {   // out [b][136] : 128 mu then 8 a_out
        *reinterpret_cast<float4*>(o4 + b * 136 + c * 16 + i0 * 4)     = m4A;
        *reinterpret_cast<float4*>(o4 + b * 136 + c * 16 + i0 * 4 + 4) = m4B;
        if (hh2 == 0) o4[b * 136 + 128 + c] = a_out;
    }
}

extern "C" void kernel_launch(void* const* d_in, const int* in_sizes, int n_in,
                              void* d_out, int out_size)
{
    const float* x  = (const float*)d_in[0];
    const float* w  = (const float*)d_in[1];
    const float* bu = (const float*)d_in[2];
    const float* ba = (const float*)d_in[3];
    float* out = (float*)d_out;

    const int batch = in_sizes[0] / 136;

    float *o1 = nullptr, *o2 = nullptr, *o3 = nullptr, *o4 = nullptr;
    if ((long long)out_size == (long long)batch * 136) {
        o4 = out;
    } else {
        o1 = out;
        o2 = o1 + (long long)batch * 128;
        o3 = o2 + (long long)batch * 8;
        o4 = o3 + (long long)batch * 136;
    }

    const int grid = (batch + 15) / 16;
    caps_kernel<<<grid, 256>>>(x, w, bu, ba, o1, o2, o3, o4, batch);
}